// round 15
// baseline (speedup 1.0000x reference)
#include <cuda_runtime.h>
#include <cuda_bf16.h>
#include <cstdint>

// Problem dims
#define BATCH 32
#define SEQ   2048
#define DIN   256
#define HID   512
#define G4H   2048
#define DOUT  256

// Recurrence: 4 batch-groups x 32 unit-groups = 128 CTAs, 512 threads each
#define NBG       4
#define R_CTAS    128
#define R_THREADS 512
#define UPG       16
#define HROW      520            // bf16 elems per h_sm row (pad 8 -> 1040 B stride)

// Scratch (device globals; allocation-free per harness rules)
__device__ float g_xg[(size_t)SEQ * BATCH * G4H];            // [s][b][g*512+u] (bias folded)
__device__ __nv_bfloat16 g_hA[(size_t)SEQ * NBG * 16 * HID]; // [s][bg][row16][u] (for K3)
__device__ __nv_bfloat16 g_hB[(size_t)SEQ * NBG * 32 * 256]; // [s][bg][prod][16 planes][16 units]
__device__ unsigned g_flag[NBG * 32];                        // per-CTA flags, one line per group

typedef unsigned long long u64;

// ---- helpers --------------------------------------------------------------
__device__ __forceinline__ u64 pack_dup(float x) {
    u64 r; asm("mov.b64 %0, {%1, %1};" : "=l"(r) : "f"(x)); return r;
}
__device__ __forceinline__ u64 ffma2(u64 a, u64 b, u64 c) {
    u64 d; asm("fma.rn.f32x2 %0, %1, %2, %3;" : "=l"(d) : "l"(a), "l"(b), "l"(c));
    return d;
}
__device__ __forceinline__ void unpack2(u64 v, float& lo, float& hi) {
    asm("mov.b64 {%0, %1}, %2;" : "=f"(lo), "=f"(hi) : "l"(v));
}
__device__ __forceinline__ unsigned ld_acq(const unsigned* p) {
    unsigned v; asm volatile("ld.acquire.gpu.global.u32 %0, [%1];" : "=r"(v) : "l"(p));
    return v;
}
__device__ __forceinline__ void st_rel(unsigned* p, unsigned v) {
    asm volatile("st.release.gpu.global.u32 [%0], %1;" :: "l"(p), "r"(v));
}
// fast transcendentals (MUFU exp; plain division — R11-proven build)
__device__ __forceinline__ float sigmoid_f(float x) {
    return 1.f / (1.f + __expf(-x));
}
__device__ __forceinline__ float tanh_f(float x) {
    return 1.f - 2.f / (__expf(2.f * x) + 1.f);
}
__device__ __forceinline__ uint32_t smem_u32(const void* p) {
    uint32_t a;
    asm("{ .reg .u64 t; cvta.to.shared.u64 t, %1; cvt.u32.u64 %0, t; }"
        : "=r"(a) : "l"(p));
    return a;
}
__device__ __forceinline__ uint32_t packbf(__nv_bfloat16 a, __nv_bfloat16 b) {
    __nv_bfloat162 t(a, b);
    return *reinterpret_cast<uint32_t*>(&t);
}

// ---------------------------------------------------------------------------
// Tiled SGEMM (64x64 tile, Kt=32) with f32x2 microkernel — R3-proven version.
// mode 0 (K1): A = x [B,S,D], row r=b*S+s; out -> g_xg[s][b][col] (+bias)
// mode 1 (K3): A reconstructed fp32 = hi+lo from g_hA; out -> y[b][s][col]
// ---------------------------------------------------------------------------
__global__ void __launch_bounds__(256)
sgemm64(const float* __restrict__ A, const float* __restrict__ Bm,
        const float* __restrict__ bias, float* __restrict__ Cout,
        int M, int N, int K, int mode)
{
    __shared__ __align__(16) float As[32 * 68];
    __shared__ __align__(16) float Bs[32 * 68];

    const int bm  = blockIdx.y * 64;
    const int bn  = blockIdx.x * 64;
    const int tid = threadIdx.x;
    const int tr  = tid >> 4;
    const int tc  = tid & 15;

    u64 acc[4][2];
#pragma unroll
    for (int i = 0; i < 4; ++i) { acc[i][0] = 0ull; acc[i][1] = 0ull; }

    for (int k0 = 0; k0 < K; k0 += 32) {
        if (mode == 0) {
#pragma unroll
            for (int j = 0; j < 8; ++j) {
                int i = tid + j * 256;
                int m = i >> 5, kk = i & 31;
                As[kk * 68 + m] = A[(size_t)(bm + m) * K + (k0 + kk)];
            }
        } else {
            // A[r][k] = fp32(hi)+fp32(lo); hi row = b&7, lo row = (b&7)+8
#pragma unroll
            for (int j = 0; j < 4; ++j) {
                int idx = tid + j * 256;       // 0..1023
                int kp  = idx & 15;            // k-pair within this 32-k block
                int m   = idx >> 4;            // 0..63
                int row = bm + m;
                int s = row >> 5, b = row & 31;
                const __nv_bfloat162* bp = (const __nv_bfloat162*)
                    (g_hA + ((size_t)s * NBG + (b >> 3)) * (16 * HID));
                int koff = (k0 >> 1) + kp;     // bf162 units within a row
                __nv_bfloat162 hi2 = bp[(b & 7) * (HID / 2) + koff];
                __nv_bfloat162 lo2 = bp[((b & 7) + 8) * (HID / 2) + koff];
                As[(kp * 2 + 0) * 68 + m] =
                    __bfloat162float(hi2.x) + __bfloat162float(lo2.x);
                As[(kp * 2 + 1) * 68 + m] =
                    __bfloat162float(hi2.y) + __bfloat162float(lo2.y);
            }
        }
#pragma unroll
        for (int j = 0; j < 8; ++j) {
            int i = tid + j * 256;
            int kk = i >> 6, n = i & 63;
            Bs[kk * 68 + n] = Bm[(size_t)(k0 + kk) * N + (bn + n)];
        }
        __syncthreads();
#pragma unroll
        for (int kk = 0; kk < 32; ++kk) {
            float4 a = *(const float4*)&As[kk * 68 + tr * 4];
            ulonglong2 b = *(const ulonglong2*)&Bs[kk * 68 + tc * 4];
            u64 a0 = pack_dup(a.x), a1 = pack_dup(a.y);
            u64 a2 = pack_dup(a.z), a3 = pack_dup(a.w);
            acc[0][0] = ffma2(a0, b.x, acc[0][0]); acc[0][1] = ffma2(a0, b.y, acc[0][1]);
            acc[1][0] = ffma2(a1, b.x, acc[1][0]); acc[1][1] = ffma2(a1, b.y, acc[1][1]);
            acc[2][0] = ffma2(a2, b.x, acc[2][0]); acc[2][1] = ffma2(a2, b.y, acc[2][1]);
            acc[3][0] = ffma2(a3, b.x, acc[3][0]); acc[3][1] = ffma2(a3, b.y, acc[3][1]);
        }
        __syncthreads();
    }

#pragma unroll
    for (int i = 0; i < 4; ++i) {
        const int row = bm + tr * 4 + i;
        float4 v;
        unpack2(acc[i][0], v.x, v.y);
        unpack2(acc[i][1], v.z, v.w);
        const int col0 = bn + tc * 4;
        v.x += bias[col0 + 0];
        v.y += bias[col0 + 1];
        v.z += bias[col0 + 2];
        v.w += bias[col0 + 3];
        if (mode == 0) {
            int bb = row >> 11;           // / SEQ
            int s  = row & (SEQ - 1);
            *(float4*)&g_xg[((size_t)s * BATCH + bb) * G4H + col0] = v;
        } else {
            int s  = row >> 5;            // / BATCH
            int bb = row & (BATCH - 1);
            *(float4*)&Cout[((size_t)bb * SEQ + s) * DOUT + col0] = v;
        }
    }
}

// ---------------------------------------------------------------------------
// Persistent LSTM recurrence — bf16-split HMMA mainloop.
// R15 structural change: PER-PRODUCER PUSH-BLOCK EXCHANGE.
//   * producer publishes its 512B h-slice as a contiguous block g_hB[t][bg][ug]
//     (plane-major [16 planes][16 units]) + release flag (unchanged array).
//   * consumer warp w waits ONLY on producers {2w, 2w+1}; as each is ready it
//     loads the 512B block (32B/lane, coalesced) and scatters into h_sm.
//     Waiting for slow producers overlaps fetching fast ones. S1 is GONE.
//   * own block: gate threads STS directly into h_sm (post-S3 safe); own
//     producer fully skipped in poll+fill (no flag RT, no L2 RT).
// Everything else (warp layout, mainloop, part reduction, flag semantics,
// 16-spin/32ns backoff) identical to the 8.41ms R11 build.
// ---------------------------------------------------------------------------
__global__ void __launch_bounds__(R_THREADS, 1)
lstm_rec_kernel(const float* __restrict__ Wh)
{
    __shared__ __align__(16) __nv_bfloat16 h_sm[16 * HROW];  // 16 rows: 8 hi + 8 lo
    __shared__ __align__(16) float part[16 * 68];            // [kh*8 + b][c], c<64

    const int tid  = threadIdx.x;
    const int bg   = blockIdx.x >> 5;
    const int ug   = blockIdx.x & 31;
    const int warp = tid >> 5;
    const int lane = tid & 31;
    const int nt   = warp & 7;            // n-tile (8 cols)
    const int kh   = warp >> 3;           // k-half (256 k)
    const int tg   = lane & 3;            // thread-in-group
    const int tq   = lane >> 2;           // group id (= batch row / B col)

    const uint32_t h_base = smem_u32(h_sm);

    // ---- Preload W fragments (hi/lo bf16 splits) into registers -----------
    // B col n = nt*8 + tq -> gate-col c = n: gate = c&3, u_l = c>>2.
    uint32_t bhi[16][2], blo[16][2];
    {
        const int n = nt * 8 + tq;
        const float* Wc = Wh + (size_t)(n & 3) * HID + ug * UPG + (n >> 2);
#pragma unroll
        for (int kt = 0; kt < 16; ++kt) {
            const int k0 = (kh * 16 + kt) * 16 + tg * 2;
            float w00 = Wc[(size_t)(k0 + 0) * G4H];
            float w01 = Wc[(size_t)(k0 + 1) * G4H];
            float w10 = Wc[(size_t)(k0 + 8) * G4H];
            float w11 = Wc[(size_t)(k0 + 9) * G4H];
            __nv_bfloat16 h00 = __float2bfloat16_rn(w00);
            __nv_bfloat16 h01 = __float2bfloat16_rn(w01);
            __nv_bfloat16 h10 = __float2bfloat16_rn(w10);
            __nv_bfloat16 h11 = __float2bfloat16_rn(w11);
            bhi[kt][0] = packbf(h00, h01);
            bhi[kt][1] = packbf(h10, h11);
            blo[kt][0] = packbf(__float2bfloat16_rn(w00 - __bfloat162float(h00)),
                                __float2bfloat16_rn(w01 - __bfloat162float(h01)));
            blo[kt][1] = packbf(__float2bfloat16_rn(w10 - __bfloat162float(h10)),
                                __float2bfloat16_rn(w11 - __bfloat162float(h11)));
        }
    }

    // Gate-thread coords (valid tid<128): coalesced map — u_g lane-inner so
    // g_hA / g_hB / h_sm stores and xg loads are contiguous runs.
    const int u_g = tid & 15;
    const int b_g = tid >> 4;
    float c_state = 0.f;

    // Consumer exchange coords: warp w covers producers {2w, 2w+1}.
    const int cons_p   = warp * 2 + (lane >> 4);   // producer handled by lane
    const int cons_row = lane & 15;                // plane row within block

    // ldmatrix lane address pieces (row = lane&15, col-block = lane>>4)
    const uint32_t lm_row = (uint32_t)(lane & 15) * (HROW * 2);
    const uint32_t lm_cb  = ((uint32_t)(lane >> 4) & 1) << 4;

    for (int t = 0; t < SEQ; ++t) {
        // Prefetch input projection for owned cell (bias folded in by K1)
        float xi = 0.f, xf = 0.f, xgv = 0.f, xo = 0.f;
        if (tid < 128) {
            const float* xp = g_xg + ((size_t)t * BATCH + bg * 8 + b_g) * G4H
                                   + ug * UPG + u_g;
            xi  = __ldcg(xp + 0 * HID);
            xf  = __ldcg(xp + 1 * HID);
            xgv = __ldcg(xp + 2 * HID);
            xo  = __ldcg(xp + 3 * HID);
        }

        float cH0 = 0.f, cH1 = 0.f, cH2 = 0.f, cH3 = 0.f;
        float cL0 = 0.f, cL1 = 0.f, cL2 = 0.f, cL3 = 0.f;

        if (t > 0) {
            // Per-warp exchange: wait on 2 producers, fetch as ready.
            // Own producer fully skipped (data already in h_sm via gate STS).
            {
                const unsigned tgt = (unsigned)t;
                const bool own = (cons_p == ug);
                int spins = 0;
                unsigned v = own ? tgt : ld_acq(&g_flag[bg * 32 + cons_p]);
                while (!__all_sync(0xffffffffu, v >= tgt)) {
                    if (++spins > 16) __nanosleep(32);
                    if (!own) v = ld_acq(&g_flag[bg * 32 + cons_p]);
                }
                if (!own) {
                    const __nv_bfloat16* src = g_hB
                        + ((size_t)(t - 1) * NBG + bg) * (32 * 256)
                        + cons_p * 256 + cons_row * 16;
                    float4 v0 = __ldcg((const float4*)src);
                    float4 v1 = __ldcg((const float4*)(src + 8));
                    *(float4*)&h_sm[cons_row * HROW + cons_p * 16]     = v0;
                    *(float4*)&h_sm[cons_row * HROW + cons_p * 16 + 8] = v1;
                }
            }
            __syncthreads();   // S2: h_sm complete

            // Tensor-core mainloop: 16 k-tiles x (1 LDSM.x4 + 2 HMMA)
#pragma unroll
            for (int kt = 0; kt < 16; ++kt) {
                const uint32_t addr = h_base + lm_row
                                    + (uint32_t)((kh * 16 + kt) * 32) + lm_cb;
                uint32_t a0, a1, a2, a3;
                asm volatile(
                    "ldmatrix.sync.aligned.m8n8.x4.shared.b16 {%0,%1,%2,%3}, [%4];"
                    : "=r"(a0), "=r"(a1), "=r"(a2), "=r"(a3) : "r"(addr));
                asm volatile(
                    "mma.sync.aligned.m16n8k16.row.col.f32.bf16.bf16.f32 "
                    "{%0,%1,%2,%3}, {%4,%5,%6,%7}, {%8,%9}, {%0,%1,%2,%3};"
                    : "+f"(cH0), "+f"(cH1), "+f"(cH2), "+f"(cH3)
                    : "r"(a0), "r"(a1), "r"(a2), "r"(a3),
                      "r"(bhi[kt][0]), "r"(bhi[kt][1]));
                asm volatile(
                    "mma.sync.aligned.m16n8k16.row.col.f32.bf16.bf16.f32 "
                    "{%0,%1,%2,%3}, {%4,%5,%6,%7}, {%8,%9}, {%0,%1,%2,%3};"
                    : "+f"(cL0), "+f"(cL1), "+f"(cL2), "+f"(cL3)
                    : "r"(a0), "r"(a1), "r"(a2), "r"(a3),
                      "r"(blo[kt][0]), "r"(blo[kt][1]));
            }

            // 3-term combine (thread-local) and store k-half partials.
            float2 sv;
            sv.x = cH0 + cH2 + cL0;   // col = nt*8 + tg*2
            sv.y = cH1 + cH3 + cL1;   // col + 1
            *(float2*)&part[(kh * 8 + tq) * 68 + nt * 8 + tg * 2] = sv;
        }
        __syncthreads();       // S3: partials visible; h_sm reads done

        if (tid < 128) {
            float4 p0 = make_float4(0.f, 0.f, 0.f, 0.f), p1 = p0;
            if (t > 0) {
                p0 = *(const float4*)&part[b_g * 68 + u_g * 4];        // kh=0
                p1 = *(const float4*)&part[(8 + b_g) * 68 + u_g * 4];  // kh=1
            }
            float ai = p0.x + p1.x + xi;
            float af = p0.y + p1.y + xf;
            float ag = p0.z + p1.z + xgv;
            float ao = p0.w + p1.w + xo;

            float ig = sigmoid_f(ai);
            float fg = sigmoid_f(af);
            float gg = tanh_f(ag);
            float og = sigmoid_f(ao);
            c_state  = fg * c_state + ig * gg;
            float hv = og * tanh_f(c_state);

            __nv_bfloat16 hhi = __float2bfloat16_rn(hv);
            __nv_bfloat16 hlo = __float2bfloat16_rn(hv - __bfloat162float(hhi));
            const int u = ug * UPG + u_g;

            // 1) history for K3 (layout unchanged)
            const size_t baseA = ((size_t)t * NBG + bg) * (16 * HID);
            g_hA[baseA + (size_t)b_g * HID + u]       = hhi;
            g_hA[baseA + (size_t)(b_g + 8) * HID + u] = hlo;

            // 2) push block for remote consumers (contiguous 512B)
            __nv_bfloat16* blk = g_hB + ((size_t)t * NBG + bg) * (32 * 256)
                                      + ug * 256;
            blk[b_g * 16 + u_g]       = hhi;
            blk[(b_g + 8) * 16 + u_g] = hlo;

            // 3) local publish: own slice straight into h_sm (post-S3 safe)
            h_sm[b_g * HROW + u]       = hhi;
            h_sm[(b_g + 8) * HROW + u] = hlo;

            // Order gate-warp stores, then publish this CTA's flag
            asm volatile("bar.sync 1, 128;" ::: "memory");
            if (tid == 0) st_rel(&g_flag[bg * 32 + ug], (unsigned)(t + 1));
        }
    }
}

// ---------------------------------------------------------------------------
extern "C" void kernel_launch(void* const* d_in, const int* in_sizes, int n_in,
                              void* d_out, int out_size)
{
    const float* x    = (const float*)d_in[0];   // [B,S,D]
    const float* Wx   = (const float*)d_in[1];   // [D,4H]
    const float* Wh   = (const float*)d_in[2];   // [H,4H]
    const float* bias = (const float*)d_in[3];   // [4H]
    const float* Wo   = (const float*)d_in[4];   // [H,O]
    const float* bo   = (const float*)d_in[5];   // [O]
    float* y = (float*)d_out;                    // [B,S,O]

    (void)in_sizes; (void)n_in; (void)out_size;

    // Reset barrier flags (graph-capturable async memset)
    void* fp = nullptr;
    cudaGetSymbolAddress(&fp, g_flag);
    cudaMemsetAsync(fp, 0, NBG * 32 * sizeof(unsigned), 0);

    // K1: xg = x @ Wx + b  (M=65536, N=2048, K=256) -> g_xg [s][b][col]
    {
        dim3 grid(G4H / 64, (BATCH * SEQ) / 64);
        sgemm64<<<grid, 256>>>(x, Wx, bias, nullptr,
                               BATCH * SEQ, G4H, DIN, 0);
    }

    // K2: persistent recurrence (push-block exchange + HMMA mainloop)
    lstm_rec_kernel<<<R_CTAS, R_THREADS>>>(Wh);

    // K3: y = h @ Wo + bo  (M=65536, N=256, K=512), A from g_hA (hi+lo)
    {
        dim3 grid(DOUT / 64, (BATCH * SEQ) / 64);
        sgemm64<<<grid, 256>>>(nullptr, Wo, bo, y,
                               SEQ * BATCH, DOUT, HID, 1);
    }
}

// round 16
// speedup vs baseline: 3.9074x; 3.9074x over previous
#include <cuda_runtime.h>
#include <cuda_bf16.h>
#include <cstdint>

// Problem dims
#define BATCH 32
#define SEQ   2048
#define DIN   256
#define HID   512
#define G4H   2048
#define DOUT  256

// Recurrence: 4 batch-groups x 32 unit-groups = 128 CTAs, 512 threads each
#define NBG       4
#define R_CTAS    128
#define R_THREADS 512
#define UPG       16
#define HROW      520            // bf16 elems per h_sm row (pad 8 -> 1040 B stride)

// Scratch (device globals; allocation-free per harness rules)
__device__ float g_xg[(size_t)SEQ * BATCH * G4H];            // [s][b][g*512+u] (bias folded)
__device__ __nv_bfloat16 g_hA[(size_t)SEQ * NBG * 16 * HID]; // [s][bg][row16][u]: rows 0-7 hi(b), 8-15 lo(b)
__device__ unsigned g_flag[NBG * 32];                        // per-CTA flags, one line per group

typedef unsigned long long u64;

// ---- helpers --------------------------------------------------------------
__device__ __forceinline__ u64 pack_dup(float x) {
    u64 r; asm("mov.b64 %0, {%1, %1};" : "=l"(r) : "f"(x)); return r;
}
__device__ __forceinline__ u64 ffma2(u64 a, u64 b, u64 c) {
    u64 d; asm("fma.rn.f32x2 %0, %1, %2, %3;" : "=l"(d) : "l"(a), "l"(b), "l"(c));
    return d;
}
__device__ __forceinline__ void unpack2(u64 v, float& lo, float& hi) {
    asm("mov.b64 {%0, %1}, %2;" : "=f"(lo), "=f"(hi) : "l"(v));
}
__device__ __forceinline__ unsigned ld_acq(const unsigned* p) {
    unsigned v; asm volatile("ld.acquire.gpu.global.u32 %0, [%1];" : "=r"(v) : "l"(p));
    return v;
}
__device__ __forceinline__ void st_rel(unsigned* p, unsigned v) {
    asm volatile("st.release.gpu.global.u32 [%0], %1;" :: "l"(p), "r"(v));
}
// fast transcendentals (MUFU exp; err ~1e-6)
__device__ __forceinline__ float sigmoid_f(float x) {
    return 1.f / (1.f + __expf(-x));
}
__device__ __forceinline__ float tanh_f(float x) {
    return 1.f - 2.f / (__expf(2.f * x) + 1.f);
}
__device__ __forceinline__ uint32_t smem_u32(const void* p) {
    uint32_t a;
    asm("{ .reg .u64 t; cvta.to.shared.u64 t, %1; cvt.u32.u64 %0, t; }"
        : "=r"(a) : "l"(p));
    return a;
}
__device__ __forceinline__ uint32_t packbf(__nv_bfloat16 a, __nv_bfloat16 b) {
    __nv_bfloat162 t(a, b);
    return *reinterpret_cast<uint32_t*>(&t);
}

// ---------------------------------------------------------------------------
// Tiled SGEMM (64x64 tile, Kt=32) with f32x2 microkernel — R3-proven version.
// mode 0 (K1): A = x [B,S,D], row r=b*S+s; out -> g_xg[s][b][col] (+bias)
// mode 1 (K3): A reconstructed fp32 = hi+lo from g_hA; out -> y[b][s][col]
// ---------------------------------------------------------------------------
__global__ void __launch_bounds__(256)
sgemm64(const float* __restrict__ A, const float* __restrict__ Bm,
        const float* __restrict__ bias, float* __restrict__ Cout,
        int M, int N, int K, int mode)
{
    __shared__ __align__(16) float As[32 * 68];
    __shared__ __align__(16) float Bs[32 * 68];

    const int bm  = blockIdx.y * 64;
    const int bn  = blockIdx.x * 64;
    const int tid = threadIdx.x;
    const int tr  = tid >> 4;
    const int tc  = tid & 15;

    u64 acc[4][2];
#pragma unroll
    for (int i = 0; i < 4; ++i) { acc[i][0] = 0ull; acc[i][1] = 0ull; }

    for (int k0 = 0; k0 < K; k0 += 32) {
        if (mode == 0) {
#pragma unroll
            for (int j = 0; j < 8; ++j) {
                int i = tid + j * 256;
                int m = i >> 5, kk = i & 31;
                As[kk * 68 + m] = A[(size_t)(bm + m) * K + (k0 + kk)];
            }
        } else {
            // A[r][k] = fp32(hi)+fp32(lo); hi row = b&7, lo row = (b&7)+8
#pragma unroll
            for (int j = 0; j < 4; ++j) {
                int idx = tid + j * 256;       // 0..1023
                int kp  = idx & 15;            // k-pair within this 32-k block
                int m   = idx >> 4;            // 0..63
                int row = bm + m;
                int s = row >> 5, b = row & 31;
                const __nv_bfloat162* bp = (const __nv_bfloat162*)
                    (g_hA + ((size_t)s * NBG + (b >> 3)) * (16 * HID));
                int koff = (k0 >> 1) + kp;     // bf162 units within a row
                __nv_bfloat162 hi2 = bp[(b & 7) * (HID / 2) + koff];
                __nv_bfloat162 lo2 = bp[((b & 7) + 8) * (HID / 2) + koff];
                As[(kp * 2 + 0) * 68 + m] =
                    __bfloat162float(hi2.x) + __bfloat162float(lo2.x);
                As[(kp * 2 + 1) * 68 + m] =
                    __bfloat162float(hi2.y) + __bfloat162float(lo2.y);
            }
        }
#pragma unroll
        for (int j = 0; j < 8; ++j) {
            int i = tid + j * 256;
            int kk = i >> 6, n = i & 63;
            Bs[kk * 68 + n] = Bm[(size_t)(k0 + kk) * N + (bn + n)];
        }
        __syncthreads();
#pragma unroll
        for (int kk = 0; kk < 32; ++kk) {
            float4 a = *(const float4*)&As[kk * 68 + tr * 4];
            ulonglong2 b = *(const ulonglong2*)&Bs[kk * 68 + tc * 4];
            u64 a0 = pack_dup(a.x), a1 = pack_dup(a.y);
            u64 a2 = pack_dup(a.z), a3 = pack_dup(a.w);
            acc[0][0] = ffma2(a0, b.x, acc[0][0]); acc[0][1] = ffma2(a0, b.y, acc[0][1]);
            acc[1][0] = ffma2(a1, b.x, acc[1][0]); acc[1][1] = ffma2(a1, b.y, acc[1][1]);
            acc[2][0] = ffma2(a2, b.x, acc[2][0]); acc[2][1] = ffma2(a2, b.y, acc[2][1]);
            acc[3][0] = ffma2(a3, b.x, acc[3][0]); acc[3][1] = ffma2(a3, b.y, acc[3][1]);
        }
        __syncthreads();
    }

#pragma unroll
    for (int i = 0; i < 4; ++i) {
        const int row = bm + tr * 4 + i;
        float4 v;
        unpack2(acc[i][0], v.x, v.y);
        unpack2(acc[i][1], v.z, v.w);
        const int col0 = bn + tc * 4;
        v.x += bias[col0 + 0];
        v.y += bias[col0 + 1];
        v.z += bias[col0 + 2];
        v.w += bias[col0 + 3];
        if (mode == 0) {
            int bb = row >> 11;           // / SEQ
            int s  = row & (SEQ - 1);
            *(float4*)&g_xg[((size_t)s * BATCH + bb) * G4H + col0] = v;
        } else {
            int s  = row >> 5;            // / BATCH
            int bb = row & (BATCH - 1);
            *(float4*)&Cout[((size_t)bb * SEQ + s) * DOUT + col0] = v;
        }
    }
}

// ---------------------------------------------------------------------------
// Persistent LSTM recurrence — bf16-split HMMA mainloop (LOCKED R11 config,
// the measured-best 8.41ms build):
//   * warp-0 poller, single flag line per group, own-flag skip,
//     16-spin/32ns backoff  (every deviation measured worse: R4/R9/R10/
//     R12/R14/R15)
//   * 16 warps: nt = w&7 (n-tile of 8 cols), kh = w>>3 (k-half of 256)
//   * k-half partials via SMEM; 4 gate warps reduce + gate math + h store
// CTA (bg, ug): batches [bg*8,+8), units [ug*16,+16) -> 64 gate-cols.
// ---------------------------------------------------------------------------
__global__ void __launch_bounds__(R_THREADS, 1)
lstm_rec_kernel(const float* __restrict__ Wh)
{
    __shared__ __align__(16) __nv_bfloat16 h_sm[16 * HROW];  // 16 rows: 8 hi + 8 lo
    __shared__ __align__(16) float part[16 * 68];            // [kh*8 + b][c], c<64

    const int tid  = threadIdx.x;
    const int bg   = blockIdx.x >> 5;
    const int ug   = blockIdx.x & 31;
    const int warp = tid >> 5;
    const int lane = tid & 31;
    const int nt   = warp & 7;            // n-tile (8 cols)
    const int kh   = warp >> 3;           // k-half (256 k)
    const int tg   = lane & 3;            // thread-in-group
    const int tq   = lane >> 2;           // group id (= batch row / B col)

    const uint32_t h_base = smem_u32(h_sm);

    // ---- Preload W fragments (hi/lo bf16 splits) into registers -----------
    // B col n = nt*8 + tq -> gate-col c = n: gate = c&3, u_l = c>>2.
    uint32_t bhi[16][2], blo[16][2];
    {
        const int n = nt * 8 + tq;
        const float* Wc = Wh + (size_t)(n & 3) * HID + ug * UPG + (n >> 2);
#pragma unroll
        for (int kt = 0; kt < 16; ++kt) {
            const int k0 = (kh * 16 + kt) * 16 + tg * 2;
            float w00 = Wc[(size_t)(k0 + 0) * G4H];
            float w01 = Wc[(size_t)(k0 + 1) * G4H];
            float w10 = Wc[(size_t)(k0 + 8) * G4H];
            float w11 = Wc[(size_t)(k0 + 9) * G4H];
            __nv_bfloat16 h00 = __float2bfloat16_rn(w00);
            __nv_bfloat16 h01 = __float2bfloat16_rn(w01);
            __nv_bfloat16 h10 = __float2bfloat16_rn(w10);
            __nv_bfloat16 h11 = __float2bfloat16_rn(w11);
            bhi[kt][0] = packbf(h00, h01);
            bhi[kt][1] = packbf(h10, h11);
            blo[kt][0] = packbf(__float2bfloat16_rn(w00 - __bfloat162float(h00)),
                                __float2bfloat16_rn(w01 - __bfloat162float(h01)));
            blo[kt][1] = packbf(__float2bfloat16_rn(w10 - __bfloat162float(h10)),
                                __float2bfloat16_rn(w11 - __bfloat162float(h11)));
        }
    }

    const int u_g = tid >> 3;    // gate-thread coords (valid tid<128), R8 map
    const int b_g = tid & 7;
    float c_state = 0.f;

    // ldmatrix lane address pieces (row = lane&15, col-block = lane>>4)
    const uint32_t lm_row = (uint32_t)(lane & 15) * (HROW * 2);
    const uint32_t lm_cb  = ((uint32_t)(lane >> 4) & 1) << 4;

    for (int t = 0; t < SEQ; ++t) {
        // Prefetch input projection for owned cell (bias folded in by K1)
        float xi = 0.f, xf = 0.f, xgv = 0.f, xo = 0.f;
        if (tid < 128) {
            const float* xp = g_xg + ((size_t)t * BATCH + bg * 8 + b_g) * G4H
                                   + ug * UPG + u_g;
            xi  = __ldcg(xp + 0 * HID);
            xf  = __ldcg(xp + 1 * HID);
            xgv = __ldcg(xp + 2 * HID);
            xo  = __ldcg(xp + 3 * HID);
        }

        float cH0 = 0.f, cH1 = 0.f, cH2 = 0.f, cH3 = 0.f;
        float cL0 = 0.f, cL1 = 0.f, cL2 = 0.f, cL3 = 0.f;

        if (t > 0) {
            // Warp 0 polls the group's flag line; own lane is treated as
            // satisfied (own ordering comes from bar.sync1 + S1 fence).
            if (tid < 32) {
                const unsigned tgt = (unsigned)t;
                const bool own = (lane == ug);
                int spins = 0;
                unsigned v = own ? tgt : ld_acq(&g_flag[bg * 32 + lane]);
                while (!__all_sync(0xffffffffu, v >= tgt)) {
                    if (++spins > 16) __nanosleep(32);
                    if (!own) v = ld_acq(&g_flag[bg * 32 + lane]);
                }
            }
            __syncthreads();   // S1

            // Fill h_sm (16 KB): warp w copies row w; lane copies 32 B
            {
                const __nv_bfloat16* src = g_hA
                    + ((size_t)(t - 1) * NBG + bg) * (16 * HID)
                    + warp * HID + lane * 16;
                float4 v0 = __ldcg((const float4*)src);
                float4 v1 = __ldcg((const float4*)(src + 8));
                *(float4*)&h_sm[warp * HROW + lane * 16]     = v0;
                *(float4*)&h_sm[warp * HROW + lane * 16 + 8] = v1;
            }
            __syncthreads();   // S2

            // Tensor-core mainloop: 16 k-tiles x (1 LDSM.x4 + 2 HMMA)
#pragma unroll
            for (int kt = 0; kt < 16; ++kt) {
                const uint32_t addr = h_base + lm_row
                                    + (uint32_t)((kh * 16 + kt) * 32) + lm_cb;
                uint32_t a0, a1, a2, a3;
                asm volatile(
                    "ldmatrix.sync.aligned.m8n8.x4.shared.b16 {%0,%1,%2,%3}, [%4];"
                    : "=r"(a0), "=r"(a1), "=r"(a2), "=r"(a3) : "r"(addr));
                asm volatile(
                    "mma.sync.aligned.m16n8k16.row.col.f32.bf16.bf16.f32 "
                    "{%0,%1,%2,%3}, {%4,%5,%6,%7}, {%8,%9}, {%0,%1,%2,%3};"
                    : "+f"(cH0), "+f"(cH1), "+f"(cH2), "+f"(cH3)
                    : "r"(a0), "r"(a1), "r"(a2), "r"(a3),
                      "r"(bhi[kt][0]), "r"(bhi[kt][1]));
                asm volatile(
                    "mma.sync.aligned.m16n8k16.row.col.f32.bf16.bf16.f32 "
                    "{%0,%1,%2,%3}, {%4,%5,%6,%7}, {%8,%9}, {%0,%1,%2,%3};"
                    : "+f"(cL0), "+f"(cL1), "+f"(cL2), "+f"(cL3)
                    : "r"(a0), "r"(a1), "r"(a2), "r"(a3),
                      "r"(blo[kt][0]), "r"(blo[kt][1]));
            }

            // 3-term combine (all thread-local) and store k-half partials.
            // C rows 0-7 = hi*W, rows 8-15 = lo*W_hi (from the Whi pass).
            float2 sv;
            sv.x = cH0 + cH2 + cL0;   // col = nt*8 + tg*2
            sv.y = cH1 + cH3 + cL1;   // col + 1
            *(float2*)&part[(kh * 8 + tq) * 68 + nt * 8 + tg * 2] = sv;
        }
        __syncthreads();       // S3: partials visible

        if (tid < 128) {
            float4 p0 = make_float4(0.f, 0.f, 0.f, 0.f), p1 = p0;
            if (t > 0) {
                p0 = *(const float4*)&part[b_g * 68 + u_g * 4];        // kh=0
                p1 = *(const float4*)&part[(8 + b_g) * 68 + u_g * 4];  // kh=1
            }
            float ai = p0.x + p1.x + xi;
            float af = p0.y + p1.y + xf;
            float ag = p0.z + p1.z + xgv;
            float ao = p0.w + p1.w + xo;

            float ig = sigmoid_f(ai);
            float fg = sigmoid_f(af);
            float gg = tanh_f(ag);
            float og = sigmoid_f(ao);
            c_state  = fg * c_state + ig * gg;
            float hv = og * tanh_f(c_state);

            // Split h to bf16 hi/lo planes for the next step's A tiles
            __nv_bfloat16 hhi = __float2bfloat16_rn(hv);
            __nv_bfloat16 hlo = __float2bfloat16_rn(hv - __bfloat162float(hhi));
            const size_t base = ((size_t)t * NBG + bg) * (16 * HID);
            const int u = ug * UPG + u_g;
            g_hA[base + (size_t)b_g * HID + u]       = hhi;
            g_hA[base + (size_t)(b_g + 8) * HID + u] = hlo;

            // Order the 4 gate-warps' h stores, then publish this CTA's flag
            asm volatile("bar.sync 1, 128;" ::: "memory");
            if (tid == 0) st_rel(&g_flag[bg * 32 + ug], (unsigned)(t + 1));
        }
    }
}

// ---------------------------------------------------------------------------
extern "C" void kernel_launch(void* const* d_in, const int* in_sizes, int n_in,
                              void* d_out, int out_size)
{
    const float* x    = (const float*)d_in[0];   // [B,S,D]
    const float* Wx   = (const float*)d_in[1];   // [D,4H]
    const float* Wh   = (const float*)d_in[2];   // [H,4H]
    const float* bias = (const float*)d_in[3];   // [4H]
    const float* Wo   = (const float*)d_in[4];   // [H,O]
    const float* bo   = (const float*)d_in[5];   // [O]
    float* y = (float*)d_out;                    // [B,S,O]

    (void)in_sizes; (void)n_in; (void)out_size;

    // Reset barrier flags (graph-capturable async memset)
    void* fp = nullptr;
    cudaGetSymbolAddress(&fp, g_flag);
    cudaMemsetAsync(fp, 0, NBG * 32 * sizeof(unsigned), 0);

    // K1: xg = x @ Wx + b  (M=65536, N=2048, K=256) -> g_xg [s][b][col]
    {
        dim3 grid(G4H / 64, (BATCH * SEQ) / 64);
        sgemm64<<<grid, 256>>>(x, Wx, bias, nullptr,
                               BATCH * SEQ, G4H, DIN, 0);
    }

    // K2: persistent recurrence (tensor-core mainloop)
    lstm_rec_kernel<<<R_CTAS, R_THREADS>>>(Wh);

    // K3: y = h @ Wo + bo  (M=65536, N=256, K=512), A from g_hA (hi+lo)
    {
        dim3 grid(DOUT / 64, (BATCH * SEQ) / 64);
        sgemm64<<<grid, 256>>>(nullptr, Wo, bo, y,
                               SEQ * BATCH, DOUT, HID, 1);
    }
}